// round 4
// baseline (speedup 1.0000x reference)
#include <cuda_runtime.h>

// GHM-C loss, algebraically collapsed:
//   loss = (1/n) * sum_b S_b / cnt_b     (the `tot` factors cancel)
// over 10 bins of g = |sigmoid(pred) - onehot|, S_b = per-bin sum of bce.
// Single fused kernel:
//   phase 1: stream all N*C elements as y=0 (g = sigmoid(x), L = log2(1+e^x))
//            into per-thread-private shared bins via fire-and-forget atomics
//   phase 2: additive correction for the N target elements (y=1), same bins
//   phase 3: block reduce -> global double atomics -> last block finalizes,
//            writes out, and re-zeros globals for the next graph replay.

#define LOG2E 1.4426950408889634f
#define LN2 0.6931471805599453

__device__ double g_sum[10];   // zeroed at static init; re-zeroed by last block
__device__ double g_cnt[10];
__device__ int g_ticket;

__device__ __forceinline__ float fex2(float x) {
    float y; asm("ex2.approx.f32 %0, %1;" : "=f"(y) : "f"(x)); return y;
}
__device__ __forceinline__ float flg2(float x) {
    float y; asm("lg2.approx.f32 %0, %1;" : "=f"(y) : "f"(x)); return y;
}
__device__ __forceinline__ float frcp(float x) {
    float y; asm("rcp.approx.f32 %0, %1;" : "=f"(y) : "f"(x)); return y;
}

// floor for y in [0,16) without F2I (keeps XU pipe clear): FADD.RM magic number.
__device__ __forceinline__ int floor_bin(float y) {
    float f = __fadd_rd(y, 8388608.0f);
    int b = __float_as_int(f) & 0xFFFF;
    return b > 9 ? 9 : b;
}

// y=0 path: g = sigmoid(x), L = log2(1 + e^x). Exactly 3 XU ops.
__device__ __forceinline__ void eval(float x, int& bi, float& L, float& g) {
    float e = fex2(x * LOG2E);
    float d = 1.0f + e;
    float r = frcp(d);
    g = e * r;
    L = flg2(d);
    bi = floor_bin(g * 10.0f);
}

__global__ void __launch_bounds__(256, 8)
ghm_kernel(const float* __restrict__ pred, const int* __restrict__ target,
           unsigned int nvec, long long total, int N, int C,
           float* __restrict__ out, int nblocks) {
    __shared__ float s_sum[10 * 256];   // 10 KB  [bin][tid]
    __shared__ float s_cnt[10 * 256];   // 10 KB
    __shared__ int s_last;
    const int tid = threadIdx.x;

#pragma unroll
    for (int b = 0; b < 10; b++) {
        s_sum[b * 256 + tid] = 0.0f;
        s_cnt[b * 256 + tid] = 0.0f;
    }
    __syncthreads();

    const unsigned int stride = gridDim.x * blockDim.x;
    const unsigned int gid = blockIdx.x * blockDim.x + tid;

    // ---- phase 1: main histogram (all elements as y=0) ----
    const float4* __restrict__ p = (const float4*)pred;
    for (unsigned int i = gid; i < nvec; i += stride) {
        float4 v = p[i];
        float xs[4] = {v.x, v.y, v.z, v.w};
#pragma unroll
        for (int k = 0; k < 4; k++) {
            int bi; float L, g;
            eval(xs[k], bi, L, g);
            int slot = bi * 256 + tid;
            atomicAdd(&s_sum[slot], L);     // own slot: no contention,
            atomicAdd(&s_cnt[slot], 1.0f);  // no return -> no RAW chain
        }
    }
    // scalar tail (total % 4 != 0 — not expected, but safe)
    for (long long j = (long long)nvec * 4 + gid; j < total; j += stride) {
        int bi; float L, g;
        eval(pred[j], bi, L, g);
        int slot = bi * 256 + tid;
        atomicAdd(&s_sum[slot], L);
        atomicAdd(&s_cnt[slot], 1.0f);
    }

    // ---- phase 2: correction for target elements (additive deltas) ----
    // element (i, target[i]) was binned as y=0; subtract that (bit-identical
    // arithmetic) and add the y=1 contribution:
    //   g1 = 1 - g0,   L1 = L0 - x*log2e
    for (unsigned int i = gid; i < (unsigned int)N; i += stride) {
        int t = target[i];
        t = t < 0 ? 0 : (t >= C ? C - 1 : t);
        float x = pred[(long long)i * C + t];
        int b0; float L0, g0;
        eval(x, b0, L0, g0);
        float g1 = fmaxf(1.0f - g0, 0.0f);
        int b1 = floor_bin(g1 * 10.0f);
        float L1 = L0 - x * LOG2E;
        atomicAdd(&s_sum[b0 * 256 + tid], -L0);
        atomicAdd(&s_cnt[b0 * 256 + tid], -1.0f);
        atomicAdd(&s_sum[b1 * 256 + tid], L1);
        atomicAdd(&s_cnt[b1 * 256 + tid], 1.0f);
    }
    __syncthreads();

    // ---- phase 3a: block tree reduce ----
    for (int off = 128; off > 0; off >>= 1) {
        if (tid < off) {
#pragma unroll
            for (int b = 0; b < 10; b++) {
                s_sum[b * 256 + tid] += s_sum[b * 256 + tid + off];
                s_cnt[b * 256 + tid] += s_cnt[b * 256 + tid + off];
            }
        }
        __syncthreads();
    }
    if (tid < 10) {
        atomicAdd(&g_sum[tid], (double)s_sum[tid * 256]);
        atomicAdd(&g_cnt[tid], (double)s_cnt[tid * 256]);
    }

    // ---- phase 3b: last block finalizes and resets globals ----
    __threadfence();
    if (tid == 0) s_last = (atomicAdd(&g_ticket, 1) == nblocks - 1) ? 1 : 0;
    __syncthreads();

    if (s_last && tid < 32) {
        double term = 0.0; int ne = 0;
        double c = 0.0, s = 0.0;
        if (tid < 10) { c = g_cnt[tid]; s = g_sum[tid]; }
        if (c > 0.5) { term = s / c; ne = 1; }
#pragma unroll
        for (int o = 16; o > 0; o >>= 1) {
            term += __shfl_down_sync(0xffffffff, term, o);
            ne   += __shfl_down_sync(0xffffffff, ne, o);
        }
        if (tid == 0) {
            if (ne < 1) ne = 1;
            out[0] = (float)(term * LN2 / (double)ne);
        }
        // reset for next graph replay (deterministic: every run starts zeroed)
        if (tid < 10) { g_sum[tid] = 0.0; g_cnt[tid] = 0.0; }
        if (tid == 0) g_ticket = 0;
    }
}

extern "C" void kernel_launch(void* const* d_in, const int* in_sizes, int n_in,
                              void* d_out, int out_size) {
    const float* pred = (const float*)d_in[0];
    const int* target = (const int*)d_in[1];
    long long total = (long long)in_sizes[0];
    int N = in_sizes[1];
    int C = (int)(total / N);
    unsigned int nvec = (unsigned int)(total >> 2);

    int blocks = 1184;   // 8 blocks x 148 SMs, single wave
    ghm_kernel<<<blocks, 256>>>(pred, target, nvec, total, N, C,
                                (float*)d_out, blocks);
}